// round 8
// baseline (speedup 1.0000x reference)
#include <cuda_runtime.h>
#include <cuda_fp16.h>
#include <cstdint>

// jordon_combined_layer: out[b] = ob + sum_u sigmoid(x[b,:]@W[:,u] + bias[u] + state*state_W[u]) * oW[u]
// B = 2097152, D = U = 64, L = 1. Output fp32 [B,1].
//
// R8: R7 was still L1-bound (73.5%, ~76us L1 busy > 65us DRAM floor) with btab
// smem reloads the largest reducible term, plus __syncthreads convoys. Fixes:
//   (1) full W fragment set persists in 64 registers/lane (loaded once) ->
//       zero B smem traffic in the loop; bands processed sequentially (af=16).
//   (2) warp-private staging: each warp LDGs its own 32 contiguous rows into
//       its own smem buffer; only __syncwarp in the loop -> free-running warps
//       keep DRAM saturated.
//   (3) __ldcs / __stcs streaming hints (zero-reuse data).

#define WITERS        4
#define WROWS         32                 // rows per warp-iteration
#define ROWS_PER_CTA  512                // 4 warps * 4 iters * 32 rows

#define SWZ(o) ((o) ^ (((o) >> 3) & 0x70))

#define MMA16816(c0, c1, c2, c3, a0, a1, a2, a3, b0, b1)                         \
    asm volatile(                                                                \
        "mma.sync.aligned.m16n8k16.row.col.f32.f16.f16.f32 "                     \
        "{%0,%1,%2,%3}, {%4,%5,%6,%7}, {%8,%9}, {%0,%1,%2,%3};"                  \
        : "+f"(c0), "+f"(c1), "+f"(c2), "+f"(c3)                                 \
        : "r"(a0), "r"(a1), "r"(a2), "r"(a3), "r"(b0), "r"(b1))

#define LDMATRIX_X4(r0, r1, r2, r3, addr)                                        \
    asm volatile("ldmatrix.sync.aligned.m8n8.x4.shared.b16 {%0,%1,%2,%3}, [%4];" \
                 : "=r"(r0), "=r"(r1), "=r"(r2), "=r"(r3) : "r"(addr))

static __device__ __forceinline__ uint32_t h2bits(__half2 h) {
    return *reinterpret_cast<uint32_t*>(&h);
}

static __device__ __forceinline__ uint32_t smem_u32(const void* p) {
    return (uint32_t)__cvta_generic_to_shared(p);
}

__global__ void __launch_bounds__(128, 5)
jordon_kernel(const float* __restrict__ x,
              const float* __restrict__ state,
              const float* __restrict__ inW,
              const float* __restrict__ stW,
              const float* __restrict__ bias,
              const float* __restrict__ outW,
              const float* __restrict__ outb,
              float* __restrict__ out) {
    // per-warp x staging: 32 rows x 128 B, SW128 swizzled  (4 KB per warp)
    __shared__ __align__(128) char xs[4][WROWS * 128];
    // W fragment table (staging only; copied to registers after one sync)
    __shared__ uint2  btab[4][8][32];
    // per-(n-tile, tg) constants: {0.5*(b+s)_u0, 0.5*oW_u0, 0.5*(b+s)_u1, 0.5*oW_u1}
    __shared__ float4 cwv[32];

    const int tid  = threadIdx.x;
    const int wid  = tid >> 5;
    const int lane = tid & 31;
    const int tg   = lane & 3;            // thread-in-group (col pair)
    const int g    = lane >> 2;           // fragment row within 8

    // ---- prologue: per-u constants ----
    if (tid < 32) {
        int j  = tid >> 2;
        int t4 = tid & 3;
        int u0 = j * 8 + t4 * 2;
        float s  = state[0];
        float s0 = s * stW[u0];
        float s1 = s * stW[u0 + 1];
        cwv[tid] = make_float4(0.5f * (bias[u0] + s0),     0.5f * outW[u0],
                               0.5f * (bias[u0 + 1] + s1), 0.5f * outW[u0 + 1]);
    }

    // ---- prologue: W fragment table, warp w builds k-step w (parallel) ----
    {
        const int k = wid;
        const int r = k * 16 + tg * 2;     // K index
#pragma unroll
        for (int j = 0; j < 8; j++) {
            int c = j * 8 + g;             // N index (u)
            __half2 lo = __floats2half2_rn(inW[(r    ) * 64 + c], inW[(r + 1) * 64 + c]);
            __half2 hi = __floats2half2_rn(inW[(r + 8) * 64 + c], inW[(r + 9) * 64 + c]);
            btab[k][j][lane] = make_uint2(h2bits(lo), h2bits(hi));
        }
    }
    __syncthreads();   // only CTA-wide sync in the kernel

    // ---- persist full W fragment set in registers (64 regs) ----
    uint2 bb[4][8];
#pragma unroll
    for (int k = 0; k < 4; k++)
#pragma unroll
        for (int j = 0; j < 8; j++)
            bb[k][j] = btab[k][j][lane];

    const float ob4 = 0.25f * outb[0];     // added once per row after 4-lane reduce

    // ldmatrix base address for band 0, k=0 (k toggles bits 5-6 via XOR;
    // band offset +2048 is swizzle-invariant, bit 11)
    const int lr  = lane & 15;
    const int lcb = (lane >> 4) * 16;
    const uint32_t a0 = smem_u32(&xs[wid][0]) + (uint32_t)SWZ(lr * 128 + lcb);

    // this warp's 128 rows: cta*512 + wid*128
    const float4* xw = reinterpret_cast<const float4*>(x) +
                       ((size_t)blockIdx.x * ROWS_PER_CTA + (size_t)wid * 128) * 16;
    const size_t  Rw = (size_t)blockIdx.x * ROWS_PER_CTA + (size_t)wid * 128;

#pragma unroll 1
    for (int it = 0; it < WITERS; it++) {
        __syncwarp();   // prior band-1 ldmatrix reads complete before restaging

        // ---- stage own 32 rows: coalesced LDG.128 -> fp16 -> STS.64 ----
        const float4* src = xw + (size_t)it * (WROWS * 16);
#pragma unroll
        for (int t = 0; t < 16; t++) {
            int i4 = lane + t * 32;        // 512 float4 per warp-tile
            int r  = i4 >> 4;
            int c4 = i4 & 15;
            float4 v = __ldcs(&src[i4]);
            uint2 hh;
            hh.x = h2bits(__floats2half2_rn(v.x, v.y));
            hh.y = h2bits(__floats2half2_rn(v.z, v.w));
            *reinterpret_cast<uint2*>(&xs[wid][0] + SWZ(r * 128 + c4 * 8)) = hh;
        }
        __syncwarp();   // STS visible to ldmatrix across lanes

        // ---- two 16-row bands, sequential (af reused: 16 regs) ----
#pragma unroll
        for (int b = 0; b < 2; b++) {
            const uint32_t ab = a0 + b * 2048;
            uint32_t af[4][4];
#pragma unroll
            for (int k = 0; k < 4; k++)
                LDMATRIX_X4(af[k][0], af[k][1], af[k][2], af[k][3],
                            ab ^ (uint32_t)(k << 5));

            float p0 = ob4, p1 = ob4;
#pragma unroll
            for (int j = 0; j < 8; j++) {
                float c0 = 0.f, c1 = 0.f, c2 = 0.f, c3 = 0.f;
                MMA16816(c0, c1, c2, c3, af[0][0], af[0][1], af[0][2], af[0][3], bb[0][j].x, bb[0][j].y);
                MMA16816(c0, c1, c2, c3, af[1][0], af[1][1], af[1][2], af[1][3], bb[1][j].x, bb[1][j].y);
                MMA16816(c0, c1, c2, c3, af[2][0], af[2][1], af[2][2], af[2][3], bb[2][j].x, bb[2][j].y);
                MMA16816(c0, c1, c2, c3, af[3][0], af[3][1], af[3][2], af[3][3], bb[3][j].x, bb[3][j].y);

                // sigmoid(z)*oW = fma(tanh(z/2), oW/2, oW/2)
                float4 w = cwv[j * 4 + tg];
                float t, v;
                v = fmaf(c0, 0.5f, w.x);
                asm("tanh.approx.f32 %0, %1;" : "=f"(t) : "f"(v));
                p0 += fmaf(t, w.y, w.y);
                v = fmaf(c1, 0.5f, w.z);
                asm("tanh.approx.f32 %0, %1;" : "=f"(t) : "f"(v));
                p0 += fmaf(t, w.w, w.w);
                v = fmaf(c2, 0.5f, w.x);
                asm("tanh.approx.f32 %0, %1;" : "=f"(t) : "f"(v));
                p1 += fmaf(t, w.y, w.y);
                v = fmaf(c3, 0.5f, w.z);
                asm("tanh.approx.f32 %0, %1;" : "=f"(t) : "f"(v));
                p1 += fmaf(t, w.w, w.w);
            }

            // reduce across the 4 lanes sharing each row (tg dimension)
            p0 += __shfl_xor_sync(0xffffffffu, p0, 1);
            p0 += __shfl_xor_sync(0xffffffffu, p0, 2);
            p1 += __shfl_xor_sync(0xffffffffu, p1, 1);
            p1 += __shfl_xor_sync(0xffffffffu, p1, 2);

            if (tg == 0) {
                size_t R = Rw + (size_t)it * WROWS + b * 16;
                __stcs(&out[R + g],     p0);
                __stcs(&out[R + g + 8], p1);
            }
        }
    }
}

extern "C" void kernel_launch(void* const* d_in, const int* in_sizes, int n_in,
                              void* d_out, int out_size) {
    const float* x     = (const float*)d_in[0];  // [B, 64]
    const float* state = (const float*)d_in[1];  // [1, 1]
    const float* inW   = (const float*)d_in[2];  // [64, 64]
    const float* stW   = (const float*)d_in[3];  // [1, 1, 64]
    const float* bias  = (const float*)d_in[4];  // [1, 64]
    const float* outW  = (const float*)d_in[5];  // [64, 1]
    const float* outb  = (const float*)d_in[6];  // [1]
    float* out = (float*)d_out;                  // [B, 1]

    int grid = out_size / ROWS_PER_CTA;          // 2097152 / 512 = 4096
    jordon_kernel<<<grid, 128>>>(x, state, inW, stW, bias, outW, outb, out);
}

// round 9
// speedup vs baseline: 1.2425x; 1.2425x over previous
#include <cuda_runtime.h>
#include <cuda_fp16.h>
#include <cstdint>

// jordon_combined_layer: out[b] = ob + sum_u sigmoid(x[b,:]@W[:,u] + bias[u] + state*state_W[u]) * oW[u]
// B = 2097152, D = U = 64, L = 1. Output fp32 [B,1].
//
// R9: R7 (102.9us) + L2 prefetch double-buffering. R8 showed that trading
// occupancy/overlap for L1 savings regresses; so keep R7's shape (6 CTAs/SM,
// CTA-wide 128-row tiles, btab amortized over 2 bands/warp) and hide the
// post-sync LDG latency by prefetching tile t+1 into L2 (no regs, no smem)
// while tile t computes. Streaming cache hints on x loads / out stores.

#define ITERS        4
#define TILE_ROWS    128
#define ROWS_PER_CTA (ITERS * TILE_ROWS)   // 512

#define SWZ(o) ((o) ^ (((o) >> 3) & 0x70))

#define MMA16816(c0, c1, c2, c3, a0, a1, a2, a3, b0, b1)                         \
    asm volatile(                                                                \
        "mma.sync.aligned.m16n8k16.row.col.f32.f16.f16.f32 "                     \
        "{%0,%1,%2,%3}, {%4,%5,%6,%7}, {%8,%9}, {%0,%1,%2,%3};"                  \
        : "+f"(c0), "+f"(c1), "+f"(c2), "+f"(c3)                                 \
        : "r"(a0), "r"(a1), "r"(a2), "r"(a3), "r"(b0), "r"(b1))

#define LDMATRIX_X4(r0, r1, r2, r3, addr)                                        \
    asm volatile("ldmatrix.sync.aligned.m8n8.x4.shared.b16 {%0,%1,%2,%3}, [%4];" \
                 : "=r"(r0), "=r"(r1), "=r"(r2), "=r"(r3) : "r"(addr))

static __device__ __forceinline__ uint32_t h2bits(__half2 h) {
    return *reinterpret_cast<uint32_t*>(&h);
}

static __device__ __forceinline__ uint32_t smem_u32(const void* p) {
    return (uint32_t)__cvta_generic_to_shared(p);
}

__global__ void __launch_bounds__(128, 6)
jordon_kernel(const float* __restrict__ x,
              const float* __restrict__ state,
              const float* __restrict__ inW,
              const float* __restrict__ stW,
              const float* __restrict__ bias,
              const float* __restrict__ outW,
              const float* __restrict__ outb,
              float* __restrict__ out) {
    // x tile as fp16, SW128 swizzled: 128 rows x 64 halfs (128 B/row) = 16 KB
    __shared__ __align__(128) char xs[TILE_ROWS * 128];
    // W fragment table: [k-step][n-tile][lane] -> {b0, b1} (half2 bit patterns)
    __shared__ uint2  btab[4][8][32];
    // per-(n-tile, tg) constants: {0.5*(b+s)_u0, 0.5*oW_u0, 0.5*(b+s)_u1, 0.5*oW_u1}
    __shared__ float4 cwv[32];
    __shared__ float  ob;

    const int tid  = threadIdx.x;
    const int wid  = tid >> 5;
    const int lane = tid & 31;
    const int tg   = lane & 3;            // thread-in-group (col pair)
    const int g    = lane >> 2;           // fragment row within 8

    // ---- prologue: per-u constants ----
    if (tid < 32) {
        int j  = tid >> 2;
        int t4 = tid & 3;
        int u0 = j * 8 + t4 * 2;
        float s  = state[0];
        float s0 = s * stW[u0];
        float s1 = s * stW[u0 + 1];
        cwv[tid] = make_float4(0.5f * (bias[u0] + s0),     0.5f * outW[u0],
                               0.5f * (bias[u0 + 1] + s1), 0.5f * outW[u0 + 1]);
    }
    if (tid == 32) ob = outb[0];

    // ---- prologue: W fragment table (warp 0 only; lane-indexed, warp-invariant) ----
    if (wid == 0) {
#pragma unroll
        for (int k = 0; k < 4; k++) {
#pragma unroll
            for (int j = 0; j < 8; j++) {
                int r = k * 16 + tg * 2;   // K index
                int c = j * 8 + g;         // N index (u)
                __half2 lo = __floats2half2_rn(inW[(r    ) * 64 + c], inW[(r + 1) * 64 + c]);
                __half2 hi = __floats2half2_rn(inW[(r + 8) * 64 + c], inW[(r + 9) * 64 + c]);
                btab[k][j][lane] = make_uint2(h2bits(lo), h2bits(hi));
            }
        }
    }

    const float4* xbase = reinterpret_cast<const float4*>(
        x + (size_t)blockIdx.x * ROWS_PER_CTA * 64);

    // ldmatrix source addresses: per band b (warp row-band = wid*32 + b*16),
    // row-within-band = lane&15, halves offset = k*16 + (lane>=16 ? 8 : 0)
    const int lr  = lane & 15;
    const int lcb = (lane >> 4) * 16;      // byte offset within k-step (0 or 16)
    const uint32_t xs_base = smem_u32(xs);
    uint32_t lm_addr[2][4];
#pragma unroll
    for (int b = 0; b < 2; b++)
#pragma unroll
        for (int k = 0; k < 4; k++)
            lm_addr[b][k] = xs_base + SWZ((wid * 32 + b * 16 + lr) * 128 + k * 32 + lcb);

#pragma unroll 1
    for (int it = 0; it < ITERS; it++) {
        // ---- stage tile: coalesced LDG.128 (512 B contiguous per warp), cvt, STS.64 ----
        const float4* src = xbase + (size_t)it * (TILE_ROWS * 16);
#pragma unroll
        for (int t = 0; t < 16; t++) {
            int i  = tid + t * 128;        // 2048 float4 per tile
            int r  = i >> 4;
            int c4 = i & 15;
            float4 v = __ldcs(&src[i]);
            uint2 hh;
            hh.x = h2bits(__floats2half2_rn(v.x, v.y));
            hh.y = h2bits(__floats2half2_rn(v.z, v.w));
            *reinterpret_cast<uint2*>(xs + SWZ(r * 128 + c4 * 8)) = hh;
        }

        // ---- prefetch tile t+1 into L2 while tile t computes (no regs/smem) ----
        if (it + 1 < ITERS) {
            const char* pf = reinterpret_cast<const char*>(
                xbase + (size_t)(it + 1) * (TILE_ROWS * 16));
            asm volatile("prefetch.global.L2 [%0];" :: "l"(pf + tid * 256));
            asm volatile("prefetch.global.L2 [%0];" :: "l"(pf + tid * 256 + 128));
        }
        __syncthreads();

        // ---- A fragments via ldmatrix.x4: 2 bands x 4 k-steps ----
        uint32_t af[2][4][4];
#pragma unroll
        for (int b = 0; b < 2; b++)
#pragma unroll
            for (int k = 0; k < 4; k++)
                LDMATRIX_X4(af[b][k][0], af[b][k][1], af[b][k][2], af[b][k][3],
                            lm_addr[b][k]);

        // ---- per n-tile: load B frags once, MMA both bands, fused epilogue ----
        float p00 = 0.f, p01 = 0.f, p10 = 0.f, p11 = 0.f;
#pragma unroll
        for (int j = 0; j < 8; j++) {
            uint2 bb0 = btab[0][j][lane];
            uint2 bb1 = btab[1][j][lane];
            uint2 bb2 = btab[2][j][lane];
            uint2 bb3 = btab[3][j][lane];
            float4 w = cwv[j * 4 + tg];

#pragma unroll
            for (int b = 0; b < 2; b++) {
                float c0 = 0.f, c1 = 0.f, c2 = 0.f, c3 = 0.f;
                MMA16816(c0, c1, c2, c3, af[b][0][0], af[b][0][1], af[b][0][2], af[b][0][3], bb0.x, bb0.y);
                MMA16816(c0, c1, c2, c3, af[b][1][0], af[b][1][1], af[b][1][2], af[b][1][3], bb1.x, bb1.y);
                MMA16816(c0, c1, c2, c3, af[b][2][0], af[b][2][1], af[b][2][2], af[b][2][3], bb2.x, bb2.y);
                MMA16816(c0, c1, c2, c3, af[b][3][0], af[b][3][1], af[b][3][2], af[b][3][3], bb3.x, bb3.y);

                // sigmoid(z)*oW = fma(tanh(z/2), oW/2, oW/2)
                float t, v;
                v = fmaf(c0, 0.5f, w.x);
                asm("tanh.approx.f32 %0, %1;" : "=f"(t) : "f"(v));
                float q0 = fmaf(t, w.y, w.y);
                v = fmaf(c1, 0.5f, w.z);
                asm("tanh.approx.f32 %0, %1;" : "=f"(t) : "f"(v));
                q0 += fmaf(t, w.w, w.w);
                v = fmaf(c2, 0.5f, w.x);
                asm("tanh.approx.f32 %0, %1;" : "=f"(t) : "f"(v));
                float q1 = fmaf(t, w.y, w.y);
                v = fmaf(c3, 0.5f, w.z);
                asm("tanh.approx.f32 %0, %1;" : "=f"(t) : "f"(v));
                q1 += fmaf(t, w.w, w.w);

                if (b == 0) { p00 += q0; p01 += q1; }
                else        { p10 += q0; p11 += q1; }
            }
        }

        // reduce across the 4 lanes sharing each row (tg dimension)
        p00 += __shfl_xor_sync(0xffffffffu, p00, 1);
        p00 += __shfl_xor_sync(0xffffffffu, p00, 2);
        p01 += __shfl_xor_sync(0xffffffffu, p01, 1);
        p01 += __shfl_xor_sync(0xffffffffu, p01, 2);
        p10 += __shfl_xor_sync(0xffffffffu, p10, 1);
        p10 += __shfl_xor_sync(0xffffffffu, p10, 2);
        p11 += __shfl_xor_sync(0xffffffffu, p11, 1);
        p11 += __shfl_xor_sync(0xffffffffu, p11, 2);

        const size_t R = (size_t)blockIdx.x * ROWS_PER_CTA + it * TILE_ROWS + wid * 32;
        if (tg == 0) {
            __stcs(&out[R + g],      p00 + ob);
            __stcs(&out[R + g + 8],  p01 + ob);
            __stcs(&out[R + g + 16], p10 + ob);
            __stcs(&out[R + g + 24], p11 + ob);
        }
        __syncthreads();   // xs reuse by next iteration's STS
    }
}

extern "C" void kernel_launch(void* const* d_in, const int* in_sizes, int n_in,
                              void* d_out, int out_size) {
    const float* x     = (const float*)d_in[0];  // [B, 64]
    const float* state = (const float*)d_in[1];  // [1, 1]
    const float* inW   = (const float*)d_in[2];  // [64, 64]
    const float* stW   = (const float*)d_in[3];  // [1, 1, 64]
    const float* bias  = (const float*)d_in[4];  // [1, 64]
    const float* outW  = (const float*)d_in[5];  // [64, 1]
    const float* outb  = (const float*)d_in[6];  // [1]
    float* out = (float*)d_out;                  // [B, 1]

    int grid = out_size / ROWS_PER_CTA;          // 2097152 / 512 = 4096
    jordon_kernel<<<grid, 128>>>(x, state, inW, stW, bias, outW, outb, out);
}